// round 7
// baseline (speedup 1.0000x reference)
#include <cuda_runtime.h>
#include <cuda_bf16.h>
#include <math.h>

#define Bz 16
#define Sz 256
#define Cz 17
#define Nz 16
#define Dz 32
#define Ez 4
#define Hz 4
#define DHz 8
#define DFFz 64
#define FULLM 0xffffffffu

// ---------------- scratch (static device memory; no allocations) -------------
__device__ float g_xns[Bz * Sz * Nz];
// q/k/v stored COMPACTED by expert: row = (b*Nz+n)*Sz + off[pe] + list_pos
__device__ float g_q[Bz * Nz * Sz * Dz];
__device__ float g_k[Bz * Nz * Sz * Dz];
__device__ float g_v[Bz * Nz * Sz * Dz];
// attention output, compacted token order: [(b*Sz + off + pos)*Nz + n]*Dz
__device__ float g_attn[Bz * Sz * Nz * Dz];
__device__ float g_z2[Bz * Sz * Nz * Dz];
__device__ float g_h1[Bz * Sz * Nz * Dz];
__device__ float g_f[Bz * Sz * Nz * DFFz];
__device__ int   g_assign[Bz * Sz];
__device__ int   g_lists[Bz * Ez * Sz];
__device__ int   g_counts[Bz * Ez];
__device__ int   g_offs[Bz * Ez];
__device__ float g_k0[Ez * Dz];
__device__ float g_v0[Ez * Dz];

// ---------------- kernel A: trend + Fourier season + new_x -------------------
__global__ void preprocess_kernel(const float* __restrict__ x) {
    int blk = blockIdx.x;
    int b = blk / Nz;
    int c = blk % Nz;
    int t = threadIdx.x;

    __shared__ float xs[Sz];
    __shared__ float ctab[Sz], stab[Sz];
    __shared__ float re_s[129], im_s[129], amp_s[129], amp2_s[129];
    __shared__ float keptre[32], keptim[32];
    __shared__ int   keptf[32];
    __shared__ int   nkept_s;
    __shared__ float thr_s;

    if (t == 0) nkept_s = 0;
    xs[t] = x[(b * Sz + t) * Cz + c];
    float ang = (float)t / 128.0f;
    ctab[t] = cospif(ang);
    stab[t] = sinpif(ang);
    __syncthreads();

    if (t < 129) {
        float re = 0.f, im = 0.f;
        for (int u = 0; u < Sz; u++) {
            int idx = (t * u) & 255;
            float xv = xs[u];
            re += xv * ctab[idx];
            im -= xv * stab[idx];
        }
        re_s[t] = re;
        im_s[t] = im;
        float a = (t == 0) ? -1e38f : sqrtf(re * re + im * im);
        amp_s[t] = a;
        amp2_s[t] = a;
    }
    __syncthreads();

    if (t < 32) {
        float thr = 0.f;
        for (int pass = 0; pass < 4; pass++) {
            unsigned long long best = 0ull;
            #pragma unroll
            for (int cc = 0; cc < 5; cc++) {
                int f = cc * 32 + t;
                if (f < 129) {
                    float a = amp2_s[f];
                    if (a > -1e37f) {
                        unsigned long long u =
                            (((unsigned long long)__float_as_uint(a)) << 32) |
                            (unsigned)f;
                        if (u > best) best = u;
                    }
                }
            }
            #pragma unroll
            for (int off = 16; off > 0; off >>= 1) {
                unsigned long long o2 = __shfl_xor_sync(FULLM, best, off);
                if (o2 > best) best = o2;
            }
            int bi = (int)(best & 0xffffffffu);
            thr = __uint_as_float((unsigned)(best >> 32));
            if (t == 0) amp2_s[bi] = -1e38f;
            __syncwarp();
        }
        if (t == 0) thr_s = thr;
    }
    __syncthreads();

    float thr = thr_s;
    if (t < 129 && amp_s[t] >= thr) {
        int p = atomicAdd(&nkept_s, 1);
        if (p < 32) {
            keptf[p] = t;
            keptre[p] = re_s[t];
            keptim[p] = im_s[t];
        }
    }
    __syncthreads();

    float season = 0.f;
    int nk = min(nkept_s, 32);
    for (int j = 0; j < nk; j++) {
        int f = keptf[j];
        float cr = keptre[j], ci = keptim[j];
        int idx = (f * t) & 255;
        if (f == 0)        season += cr;
        else if (f == 128) season += cr * ctab[idx];
        else               season += 2.f * (cr * ctab[idx] - ci * stab[idx]);
    }
    season *= (1.0f / 256.0f);

    float s4 = 0.f, s8 = 0.f, s12 = 0.f;
    #pragma unroll
    for (int i = -1; i <= 2; i++) { int u = min(max(t + i, 0), Sz - 1); s4 += xs[u]; }
    #pragma unroll
    for (int i = -3; i <= 4; i++) { int u = min(max(t + i, 0), Sz - 1); s8 += xs[u]; }
    #pragma unroll
    for (int i = -5; i <= 6; i++) { int u = min(max(t + i, 0), Sz - 1); s12 += xs[u]; }
    float trend = (s4 * 0.25f + s8 * 0.125f + s12 * (1.0f / 12.0f)) * (1.0f / 3.0f);

    g_xns[(b * Sz + t) * Nz + c] = xs[t] + season + trend;
}

// ---------------- kernel B: routing + lists + offsets + k0/v0 ----------------
__global__ void assign_kernel(const float* __restrict__ ox,
                              const float* __restrict__ start_b,
                              const float* __restrict__ ln1_g,
                              const float* __restrict__ ln1_b,
                              const float* __restrict__ Wk,
                              const float* __restrict__ Wv) {
    int t = threadIdx.x;
    __shared__ float red[256];
    __shared__ float smin_s, smax_s;

    float mn = 3.4e38f, mx = -3.4e38f;
    for (int i = t; i < Bz * Sz; i += 256) {
        float s = ox[i * 2 + 1];
        mn = fminf(mn, s);
        mx = fmaxf(mx, s);
    }
    red[t] = mn; __syncthreads();
    for (int o = 128; o > 0; o >>= 1) {
        if (t < o) red[t] = fminf(red[t], red[t + o]);
        __syncthreads();
    }
    if (t == 0) smin_s = red[0];
    __syncthreads();
    red[t] = mx; __syncthreads();
    for (int o = 128; o > 0; o >>= 1) {
        if (t < o) red[t] = fmaxf(red[t], red[t + o]);
        __syncthreads();
    }
    if (t == 0) smax_s = red[0];
    __syncthreads();

    float bmin = smin_s, bmax = smax_s;
    float step = (bmax - bmin) * 0.25f;
    for (int i = t; i < Bz * Sz; i += 256) {
        float s = ox[i * 2 + 1];
        int cntb = 0;
        #pragma unroll
        for (int k = 0; k < 5; k++) {
            float bv = bmin + step * (float)k;
            if (bv <= s) cntb++;
        }
        int a = cntb - 1;
        a = max(0, min(Ez - 1, a));
        g_assign[i] = a;
    }
    __syncthreads();

    int warp = t >> 5, lane = t & 31;
    for (int pe = warp; pe < Bz * Ez; pe += 8) {
        int b = pe / Ez, e = pe % Ez;
        int cnt = 0;
        for (int s0 = 0; s0 < Sz; s0 += 32) {
            int s = s0 + lane;
            int a = g_assign[b * Sz + s];
            unsigned bal = __ballot_sync(FULLM, a == e);
            int pos = cnt + __popc(bal & ((1u << lane) - 1u));
            if (a == e) g_lists[pe * Sz + pos] = s;
            cnt += __popc(bal);
        }
        if (lane == 0) g_counts[pe] = cnt;
    }
    __syncthreads();

    // per-b prefix offsets over experts
    if (t < Bz) {
        int off = 0;
        #pragma unroll
        for (int e = 0; e < Ez; e++) {
            g_offs[t * Ez + e] = off;
            off += g_counts[t * Ez + e];
        }
    }

    if (t < Ez * Dz) {
        int e = t / Dz, d = t % Dz;
        float m = 0.f;
        for (int i = 0; i < Dz; i++) m += start_b[i];
        m *= (1.0f / Dz);
        float var = 0.f;
        for (int i = 0; i < Dz; i++) { float dd = start_b[i] - m; var += dd * dd; }
        var *= (1.0f / Dz);
        float rs = rsqrtf(var + 1e-5f);
        float k0 = 0.f, v0 = 0.f;
        for (int i = 0; i < Dz; i++) {
            float z = (start_b[i] - m) * rs * ln1_g[e * Dz + i] + ln1_b[e * Dz + i];
            k0 += z * Wk[(e * Dz + i) * Dz + d];
            v0 += z * Wv[(e * Dz + i) * Dz + d];
        }
        g_k0[e * Dz + d] = k0;
        g_v0[e * Dz + d] = v0;
    }
}

// ---------------- kernel C: expert-grouped LN1 + Q/K/V (compacted writes) ----
__global__ __launch_bounds__(128) void qkv_kernel(const float* __restrict__ sW,
                                                  const float* __restrict__ sb,
                                                  const float* __restrict__ Wq,
                                                  const float* __restrict__ Wk,
                                                  const float* __restrict__ Wv,
                                                  const float* __restrict__ ln1_g,
                                                  const float* __restrict__ ln1_b) {
    int blk = blockIdx.x;
    int pe = blk >> 3, tile = blk & 7;
    int b = pe / Ez, e = pe % Ez;
    int cnt = g_counts[pe];
    int off = g_offs[pe];
    int t = threadIdx.x;

    __shared__ float Ws[3][Dz * Dz];
    __shared__ float zs[Nz][Dz];
    __shared__ float g1s[Dz], bl1s[Dz], sWs[Dz], sbs[Dz];

    for (int i = t; i < Dz * Dz; i += 128) {
        Ws[0][i] = Wq[e * Dz * Dz + i];
        Ws[1][i] = Wk[e * Dz * Dz + i];
        Ws[2][i] = Wv[e * Dz * Dz + i];
    }
    if (t < Dz) {
        g1s[t] = ln1_g[e * Dz + t];
        bl1s[t] = ln1_b[e * Dz + t];
        sWs[t] = sW[t];
        sbs[t] = sb[t];
    }
    __syncthreads();

    const int* lst = &g_lists[pe * Sz];
    for (int ti = tile; ti < cnt; ti += 8) {
        int s = lst[ti];
        if (t < Nz) {
            float a = g_xns[(b * Sz + s) * Nz + t];
            float h[Dz];
            float m = 0.f;
            #pragma unroll
            for (int i = 0; i < Dz; i++) { h[i] = a * sWs[i] + sbs[i]; m += h[i]; }
            m *= (1.0f / Dz);
            float var = 0.f;
            #pragma unroll
            for (int i = 0; i < Dz; i++) { float d = h[i] - m; var += d * d; }
            var *= (1.0f / Dz);
            float rs = rsqrtf(var + 1e-5f);
            #pragma unroll
            for (int i = 0; i < Dz; i++)
                zs[t][i] = (h[i] - m) * rs * g1s[i] + bl1s[i];
        }
        __syncthreads();

        for (int o = t; o < 3 * Nz * Dz; o += 128) {
            int mat = o >> 9;
            int r = o & 511;
            int n = r >> 5, d = r & 31;
            const float* W = Ws[mat];
            float acc = 0.f;
            #pragma unroll
            for (int i = 0; i < Dz; i++) acc += zs[n][i] * W[i * Dz + d];
            float* dst = (mat == 0) ? g_q : ((mat == 1) ? g_k : g_v);
            dst[((b * Nz + n) * Sz + off + ti) * Dz + d] = acc;   // compacted
        }
        __syncthreads();
    }
}

// ---------------- kernel D: attention (1 warp = 1 query chunk) ---------------
// grid = Bz*Ez*Nz*8 (chunk in low bits); 32 threads; contiguous compacted keys
__global__ __launch_bounds__(32, 16) void attn_kernel() {
    int blk = blockIdx.x;
    int chunk = blk & 7;
    int n = (blk >> 3) & (Nz - 1);
    int pe = blk >> 7;
    int cnt = g_counts[pe];
    if (chunk * 32 >= cnt) return;
    int off = g_offs[pe];
    int b = pe / Ez, e = pe % Ez;
    int lane = threadIdx.x;

    __shared__ float k0s[Dz], v0s[Dz];
    k0s[lane] = g_k0[e * Dz + lane];
    v0s[lane] = g_v0[e * Dz + lane];
    __syncwarp();

    int qi = chunk * 32 + lane;
    bool active = qi < cnt;
    int qclamp = active ? qi : (cnt - 1);
    long base = (long)(b * Nz + n) * Sz + off;

    const float scale = 0.35355339059327373f;   // 1/sqrt(8)
    float fnbg = (float)(Sz - cnt);

    float qv[Dz];
    {
        const float4* qg = (const float4*)(g_q + (base + qclamp) * Dz);
        #pragma unroll
        for (int f = 0; f < 8; f++) {
            float4 v = __ldg(qg + f);
            qv[f * 4 + 0] = v.x; qv[f * 4 + 1] = v.y;
            qv[f * 4 + 2] = v.z; qv[f * 4 + 3] = v.w;
        }
    }

    float l0[Hz], den[Hz], o[Hz][DHz];
    #pragma unroll
    for (int h = 0; h < Hz; h++) {
        float l = 0.f;
        #pragma unroll
        for (int i = 0; i < DHz; i++) l += qv[h * 8 + i] * k0s[h * 8 + i];
        l0[h] = l * scale;
        den[h] = fnbg;
        #pragma unroll
        for (int i = 0; i < DHz; i++) o[h][i] = fnbg * v0s[h * 8 + i];
    }

    // contiguous key/value stream (compacted layout)
    const float4* kb = (const float4*)(g_k + base * Dz);
    const float4* vb = (const float4*)(g_v + base * Dz);
    #pragma unroll 2
    for (int j = 0; j < cnt; j++) {
        const float4* kr = kb + j * 8;
        const float4* vr = vb + j * 8;
        #pragma unroll
        for (int h = 0; h < Hz; h++) {
            float4 a = __ldg(kr + h * 2), cc = __ldg(kr + h * 2 + 1);
            float l = qv[h*8+0]*a.x + qv[h*8+1]*a.y + qv[h*8+2]*a.z + qv[h*8+3]*a.w
                    + qv[h*8+4]*cc.x + qv[h*8+5]*cc.y + qv[h*8+6]*cc.z + qv[h*8+7]*cc.w;
            float w = __expf(l * scale - l0[h]);
            den[h] += w;
            float4 va = __ldg(vr + h * 2), vc = __ldg(vr + h * 2 + 1);
            o[h][0] += w * va.x; o[h][1] += w * va.y;
            o[h][2] += w * va.z; o[h][3] += w * va.w;
            o[h][4] += w * vc.x; o[h][5] += w * vc.y;
            o[h][6] += w * vc.z; o[h][7] += w * vc.w;
        }
    }

    if (active) {
        long gpos = (long)b * Sz + off + qi;    // compacted token index
        float4* dst = (float4*)(g_attn + (gpos * Nz + n) * Dz);
        #pragma unroll
        for (int h = 0; h < Hz; h++) {
            float inv = 1.0f / den[h];
            dst[h * 2]     = make_float4(o[h][0]*inv, o[h][1]*inv,
                                         o[h][2]*inv, o[h][3]*inv);
            dst[h * 2 + 1] = make_float4(o[h][4]*inv, o[h][5]*inv,
                                         o[h][6]*inv, o[h][7]*inv);
        }
    }
}

// ---------------- kernel E1: Wo + LN2 -> z2, h1(+b2) -------------------------
// grid = (b,e)*16 tiles; 128 thr (4 warps x 4 channels); lane = dim
__global__ __launch_bounds__(128, 6) void tail1_kernel(
        const float* __restrict__ sW,  const float* __restrict__ sb,
        const float* __restrict__ Wo,  const float* __restrict__ ln2_g,
        const float* __restrict__ ln2_b, const float* __restrict__ b2) {
    int blk = blockIdx.x;
    int pe = blk >> 4, tile = blk & 15;
    int b = pe / Ez, e = pe % Ez;
    int cnt = g_counts[pe];
    if (cnt == 0) return;
    int off = g_offs[pe];
    int t = threadIdx.x, warp = t >> 5, lane = t & 31;

    __shared__ float att_s[4][4][Dz];

    float wo[Dz];
    #pragma unroll
    for (int i = 0; i < Dz; i++)
        wo[i] = __ldg(&Wo[e * Dz * Dz + i * Dz + lane]);

    const float sWl  = __ldg(&sW[lane]);
    const float sbl  = __ldg(&sb[lane]);
    const float g2l  = __ldg(&ln2_g[e * Dz + lane]);
    const float bl2l = __ldg(&ln2_b[e * Dz + lane]);
    const float b2l  = __ldg(&b2[e * Dz + lane]);

    const int* lst = &g_lists[pe * Sz];
    int n0 = warp * 4;

    for (int ti = tile; ti < cnt; ti += 16) {
        int s = lst[ti];
        long gpos = (long)b * Sz + off + ti;

        #pragma unroll
        for (int ch = 0; ch < 4; ch++)
            att_s[warp][ch][lane] =
                g_attn[(gpos * Nz + n0 + ch) * Dz + lane];
        __syncwarp();

        #pragma unroll
        for (int ch = 0; ch < 4; ch++) {
            float xv = __ldg(&g_xns[((long)b * Sz + s) * Nz + n0 + ch]);
            float h1 = xv * sWl + sbl;
            const float4* ap = (const float4*)att_s[warp][ch];
            #pragma unroll
            for (int j4 = 0; j4 < 8; j4++) {
                float4 a = ap[j4];
                h1 += a.x * wo[j4 * 4 + 0] + a.y * wo[j4 * 4 + 1]
                    + a.z * wo[j4 * 4 + 2] + a.w * wo[j4 * 4 + 3];
            }
            float mu = h1;
            #pragma unroll
            for (int o2 = 16; o2 > 0; o2 >>= 1)
                mu += __shfl_xor_sync(FULLM, mu, o2);
            mu *= (1.0f / Dz);
            float df = h1 - mu;
            float var = df * df;
            #pragma unroll
            for (int o2 = 16; o2 > 0; o2 >>= 1)
                var += __shfl_xor_sync(FULLM, var, o2);
            var *= (1.0f / Dz);
            float z = df * rsqrtf(var + 1e-5f) * g2l + bl2l;
            g_z2[(gpos * Nz + n0 + ch) * Dz + lane] = z;
            g_h1[(gpos * Nz + n0 + ch) * Dz + lane] = h1 + b2l;
        }
        __syncwarp();
    }
}

// ---------------- kernel E2: FFN layer 1 -> f = relu(z2@W1 + b1) -------------
// lane = 2 f-columns (lane, lane+32)
__global__ __launch_bounds__(128, 5) void tail2_kernel(
        const float* __restrict__ W1, const float* __restrict__ b1) {
    int blk = blockIdx.x;
    int pe = blk >> 4, tile = blk & 15;
    int b = pe / Ez, e = pe % Ez;
    int cnt = g_counts[pe];
    if (cnt == 0) return;
    int off = g_offs[pe];
    int t = threadIdx.x, warp = t >> 5, lane = t & 31;

    __shared__ float z2_s[4][4][Dz];

    float w1a[Dz], w1b[Dz];
    #pragma unroll
    for (int i = 0; i < Dz; i++) {
        w1a[i] = __ldg(&W1[e * Dz * DFFz + i * DFFz + lane]);
        w1b[i] = __ldg(&W1[e * Dz * DFFz + i * DFFz + 32 + lane]);
    }
    const float b1a = __ldg(&b1[e * DFFz + lane]);
    const float b1b = __ldg(&b1[e * DFFz + 32 + lane]);

    int n0 = warp * 4;
    for (int ti = tile; ti < cnt; ti += 16) {
        long gpos = (long)b * Sz + off + ti;
        #pragma unroll
        for (int ch = 0; ch < 4; ch++)
            z2_s[warp][ch][lane] = g_z2[(gpos * Nz + n0 + ch) * Dz + lane];
        __syncwarp();

        #pragma unroll
        for (int ch = 0; ch < 4; ch++) {
            float f0 = b1a, f1 = b1b;
            const float4* zp = (const float4*)z2_s[warp][ch];
            #pragma unroll
            for (int i4 = 0; i4 < 8; i4++) {
                float4 z = zp[i4];
                f0 += z.x * w1a[i4*4+0] + z.y * w1a[i4*4+1]
                    + z.z * w1a[i4*4+2] + z.w * w1a[i4*4+3];
                f1 += z.x * w1b[i4*4+0] + z.y * w1b[i4*4+1]
                    + z.z * w1b[i4*4+2] + z.w * w1b[i4*4+3];
            }
            g_f[(gpos * Nz + n0 + ch) * DFFz + lane]      = fmaxf(f0, 0.f);
            g_f[(gpos * Nz + n0 + ch) * DFFz + 32 + lane] = fmaxf(f1, 0.f);
        }
        __syncwarp();
    }
}

// ---------------- kernel E3: FFN layer 2 -> out = h1 + f@W2 ------------------
__global__ __launch_bounds__(128, 5) void tail3_kernel(
        const float* __restrict__ W2, float* __restrict__ out) {
    int blk = blockIdx.x;
    int pe = blk >> 4, tile = blk & 15;
    int b = pe / Ez, e = pe % Ez;
    int cnt = g_counts[pe];
    if (cnt == 0) return;
    int off = g_offs[pe];
    int t = threadIdx.x, warp = t >> 5, lane = t & 31;

    __shared__ float f_s[4][4][DFFz];

    float w2[DFFz];
    #pragma unroll
    for (int j = 0; j < DFFz; j++)
        w2[j] = __ldg(&W2[e * DFFz * Dz + j * Dz + lane]);

    const int* lst = &g_lists[pe * Sz];
    int n0 = warp * 4;

    for (int ti = tile; ti < cnt; ti += 16) {
        int s = lst[ti];
        long gpos = (long)b * Sz + off + ti;
        #pragma unroll
        for (int ch = 0; ch < 4; ch++) {
            f_s[warp][ch][lane]      = g_f[(gpos * Nz + n0 + ch) * DFFz + lane];
            f_s[warp][ch][32 + lane] = g_f[(gpos * Nz + n0 + ch) * DFFz + 32 + lane];
        }
        __syncwarp();

        #pragma unroll
        for (int ch = 0; ch < 4; ch++) {
            float acc = g_h1[(gpos * Nz + n0 + ch) * Dz + lane];
            const float4* fp = (const float4*)f_s[warp][ch];
            #pragma unroll
            for (int j4 = 0; j4 < 16; j4++) {
                float4 f = fp[j4];
                acc += f.x * w2[j4*4+0] + f.y * w2[j4*4+1]
                     + f.z * w2[j4*4+2] + f.w * w2[j4*4+3];
            }
            out[(((long)b * Sz + s) * Nz + n0 + ch) * Dz + lane] = acc;
        }
        __syncwarp();
    }
}

// ---------------- launch ------------------------------------------------------
extern "C" void kernel_launch(void* const* d_in, const int* in_sizes, int n_in,
                              void* d_out, int out_size) {
    const float* x        = (const float*)d_in[0];
    const float* ox       = (const float*)d_in[1];
    const float* start_W  = (const float*)d_in[2];
    const float* start_b  = (const float*)d_in[3];
    const float* Wq       = (const float*)d_in[4];
    const float* Wk       = (const float*)d_in[5];
    const float* Wv       = (const float*)d_in[6];
    const float* Wo       = (const float*)d_in[7];
    const float* ln1_g    = (const float*)d_in[8];
    const float* ln1_b    = (const float*)d_in[9];
    const float* ln2_g    = (const float*)d_in[10];
    const float* ln2_b    = (const float*)d_in[11];
    const float* W1       = (const float*)d_in[12];
    const float* b1       = (const float*)d_in[13];
    const float* W2       = (const float*)d_in[14];
    const float* b2       = (const float*)d_in[15];
    float* out = (float*)d_out;

    preprocess_kernel<<<Bz * Nz, 256>>>(x);
    assign_kernel<<<1, 256>>>(ox, start_b, ln1_g, ln1_b, Wk, Wv);
    qkv_kernel<<<Bz * Ez * 8, 128>>>(start_W, start_b, Wq, Wk, Wv, ln1_g, ln1_b);
    attn_kernel<<<Bz * Ez * Nz * 8, 32>>>();
    tail1_kernel<<<Bz * Ez * 16, 128>>>(start_W, start_b, Wo, ln2_g, ln2_b, b2);
    tail2_kernel<<<Bz * Ez * 16, 128>>>(W1, b1);
    tail3_kernel<<<Bz * Ez * 16, 128>>>(W2, out);
}

// round 9
// speedup vs baseline: 1.0838x; 1.0838x over previous
#include <cuda_runtime.h>
#include <cuda_bf16.h>
#include <math.h>

#define Bz 16
#define Sz 256
#define Cz 17
#define Nz 16
#define Dz 32
#define Ez 4
#define Hz 4
#define DHz 8
#define DFFz 64
#define FULLM 0xffffffffu

// ---------------- scratch (static device memory; no allocations) -------------
__device__ float g_xns[Bz * Sz * Nz];
// q/k/v stored COMPACTED by expert: row = (b*Nz+n)*Sz + off[pe] + list_pos
__device__ float g_q[Bz * Nz * Sz * Dz];
__device__ float g_k[Bz * Nz * Sz * Dz];
__device__ float g_v[Bz * Nz * Sz * Dz];
// attention output, compacted token order: [(b*Sz + off + pos)*Nz + n]*Dz
__device__ float g_attn[Bz * Sz * Nz * Dz];
__device__ float g_z2[Bz * Sz * Nz * Dz];
__device__ float g_h1[Bz * Sz * Nz * Dz];
__device__ float g_f[Bz * Sz * Nz * DFFz];
__device__ int   g_assign[Bz * Sz];
__device__ int   g_lists[Bz * Ez * Sz];
__device__ int   g_counts[Bz * Ez];
__device__ int   g_offs[Bz * Ez];
__device__ float g_k0[Ez * Dz];
__device__ float g_v0[Ez * Dz];

// ---------------- kernel A: trend + Fourier season + new_x -------------------
__global__ void preprocess_kernel(const float* __restrict__ x) {
    int blk = blockIdx.x;
    int b = blk / Nz;
    int c = blk % Nz;
    int t = threadIdx.x;

    __shared__ float xs[Sz];
    __shared__ float ctab[Sz], stab[Sz];
    __shared__ float re_s[129], im_s[129], amp_s[129], amp2_s[129];
    __shared__ float keptre[32], keptim[32];
    __shared__ int   keptf[32];
    __shared__ int   nkept_s;
    __shared__ float thr_s;

    if (t == 0) nkept_s = 0;
    xs[t] = x[(b * Sz + t) * Cz + c];
    float ang = (float)t / 128.0f;
    ctab[t] = cospif(ang);
    stab[t] = sinpif(ang);
    __syncthreads();

    if (t < 129) {
        float re = 0.f, im = 0.f;
        for (int u = 0; u < Sz; u++) {
            int idx = (t * u) & 255;
            float xv = xs[u];
            re += xv * ctab[idx];
            im -= xv * stab[idx];
        }
        re_s[t] = re;
        im_s[t] = im;
        float a = (t == 0) ? -1e38f : sqrtf(re * re + im * im);
        amp_s[t] = a;
        amp2_s[t] = a;
    }
    __syncthreads();

    if (t < 32) {
        float thr = 0.f;
        for (int pass = 0; pass < 4; pass++) {
            unsigned long long best = 0ull;
            #pragma unroll
            for (int cc = 0; cc < 5; cc++) {
                int f = cc * 32 + t;
                if (f < 129) {
                    float a = amp2_s[f];
                    if (a > -1e37f) {
                        unsigned long long u =
                            (((unsigned long long)__float_as_uint(a)) << 32) |
                            (unsigned)f;
                        if (u > best) best = u;
                    }
                }
            }
            #pragma unroll
            for (int off = 16; off > 0; off >>= 1) {
                unsigned long long o2 = __shfl_xor_sync(FULLM, best, off);
                if (o2 > best) best = o2;
            }
            int bi = (int)(best & 0xffffffffu);
            thr = __uint_as_float((unsigned)(best >> 32));
            if (t == 0) amp2_s[bi] = -1e38f;
            __syncwarp();
        }
        if (t == 0) thr_s = thr;
    }
    __syncthreads();

    float thr = thr_s;
    if (t < 129 && amp_s[t] >= thr) {
        int p = atomicAdd(&nkept_s, 1);
        if (p < 32) {
            keptf[p] = t;
            keptre[p] = re_s[t];
            keptim[p] = im_s[t];
        }
    }
    __syncthreads();

    float season = 0.f;
    int nk = min(nkept_s, 32);
    for (int j = 0; j < nk; j++) {
        int f = keptf[j];
        float cr = keptre[j], ci = keptim[j];
        int idx = (f * t) & 255;
        if (f == 0)        season += cr;
        else if (f == 128) season += cr * ctab[idx];
        else               season += 2.f * (cr * ctab[idx] - ci * stab[idx]);
    }
    season *= (1.0f / 256.0f);

    float s4 = 0.f, s8 = 0.f, s12 = 0.f;
    #pragma unroll
    for (int i = -1; i <= 2; i++) { int u = min(max(t + i, 0), Sz - 1); s4 += xs[u]; }
    #pragma unroll
    for (int i = -3; i <= 4; i++) { int u = min(max(t + i, 0), Sz - 1); s8 += xs[u]; }
    #pragma unroll
    for (int i = -5; i <= 6; i++) { int u = min(max(t + i, 0), Sz - 1); s12 += xs[u]; }
    float trend = (s4 * 0.25f + s8 * 0.125f + s12 * (1.0f / 12.0f)) * (1.0f / 3.0f);

    g_xns[(b * Sz + t) * Nz + c] = xs[t] + season + trend;
}

// ---------------- kernel B: routing + lists + offsets + k0/v0 ----------------
__global__ void assign_kernel(const float* __restrict__ ox,
                              const float* __restrict__ start_b,
                              const float* __restrict__ ln1_g,
                              const float* __restrict__ ln1_b,
                              const float* __restrict__ Wk,
                              const float* __restrict__ Wv) {
    int t = threadIdx.x;
    __shared__ float red[256];
    __shared__ float smin_s, smax_s;

    float mn = 3.4e38f, mx = -3.4e38f;
    for (int i = t; i < Bz * Sz; i += 256) {
        float s = ox[i * 2 + 1];
        mn = fminf(mn, s);
        mx = fmaxf(mx, s);
    }
    red[t] = mn; __syncthreads();
    for (int o = 128; o > 0; o >>= 1) {
        if (t < o) red[t] = fminf(red[t], red[t + o]);
        __syncthreads();
    }
    if (t == 0) smin_s = red[0];
    __syncthreads();
    red[t] = mx; __syncthreads();
    for (int o = 128; o > 0; o >>= 1) {
        if (t < o) red[t] = fmaxf(red[t], red[t + o]);
        __syncthreads();
    }
    if (t == 0) smax_s = red[0];
    __syncthreads();

    float bmin = smin_s, bmax = smax_s;
    float step = (bmax - bmin) * 0.25f;
    for (int i = t; i < Bz * Sz; i += 256) {
        float s = ox[i * 2 + 1];
        int cntb = 0;
        #pragma unroll
        for (int k = 0; k < 5; k++) {
            float bv = bmin + step * (float)k;
            if (bv <= s) cntb++;
        }
        int a = cntb - 1;
        a = max(0, min(Ez - 1, a));
        g_assign[i] = a;
    }
    __syncthreads();

    int warp = t >> 5, lane = t & 31;
    for (int pe = warp; pe < Bz * Ez; pe += 8) {
        int b = pe / Ez, e = pe % Ez;
        int cnt = 0;
        for (int s0 = 0; s0 < Sz; s0 += 32) {
            int s = s0 + lane;
            int a = g_assign[b * Sz + s];
            unsigned bal = __ballot_sync(FULLM, a == e);
            int pos = cnt + __popc(bal & ((1u << lane) - 1u));
            if (a == e) g_lists[pe * Sz + pos] = s;
            cnt += __popc(bal);
        }
        if (lane == 0) g_counts[pe] = cnt;
    }
    __syncthreads();

    // per-b prefix offsets over experts
    if (t < Bz) {
        int off = 0;
        #pragma unroll
        for (int e = 0; e < Ez; e++) {
            g_offs[t * Ez + e] = off;
            off += g_counts[t * Ez + e];
        }
    }

    if (t < Ez * Dz) {
        int e = t / Dz, d = t % Dz;
        float m = 0.f;
        for (int i = 0; i < Dz; i++) m += start_b[i];
        m *= (1.0f / Dz);
        float var = 0.f;
        for (int i = 0; i < Dz; i++) { float dd = start_b[i] - m; var += dd * dd; }
        var *= (1.0f / Dz);
        float rs = rsqrtf(var + 1e-5f);
        float k0 = 0.f, v0 = 0.f;
        for (int i = 0; i < Dz; i++) {
            float z = (start_b[i] - m) * rs * ln1_g[e * Dz + i] + ln1_b[e * Dz + i];
            k0 += z * Wk[(e * Dz + i) * Dz + d];
            v0 += z * Wv[(e * Dz + i) * Dz + d];
        }
        g_k0[e * Dz + d] = k0;
        g_v0[e * Dz + d] = v0;
    }
}

// ---------------- kernel C: expert-grouped LN1 + Q/K/V (compacted writes) ----
__global__ __launch_bounds__(128) void qkv_kernel(const float* __restrict__ sW,
                                                  const float* __restrict__ sb,
                                                  const float* __restrict__ Wq,
                                                  const float* __restrict__ Wk,
                                                  const float* __restrict__ Wv,
                                                  const float* __restrict__ ln1_g,
                                                  const float* __restrict__ ln1_b) {
    int blk = blockIdx.x;
    int pe = blk >> 3, tile = blk & 7;
    int b = pe / Ez, e = pe % Ez;
    int cnt = g_counts[pe];
    int off = g_offs[pe];
    int t = threadIdx.x;

    __shared__ float Ws[3][Dz * Dz];
    __shared__ float zs[Nz][Dz];
    __shared__ float g1s[Dz], bl1s[Dz], sWs[Dz], sbs[Dz];

    for (int i = t; i < Dz * Dz; i += 128) {
        Ws[0][i] = Wq[e * Dz * Dz + i];
        Ws[1][i] = Wk[e * Dz * Dz + i];
        Ws[2][i] = Wv[e * Dz * Dz + i];
    }
    if (t < Dz) {
        g1s[t] = ln1_g[e * Dz + t];
        bl1s[t] = ln1_b[e * Dz + t];
        sWs[t] = sW[t];
        sbs[t] = sb[t];
    }
    __syncthreads();

    const int* lst = &g_lists[pe * Sz];
    for (int ti = tile; ti < cnt; ti += 8) {
        int s = lst[ti];
        if (t < Nz) {
            float a = g_xns[(b * Sz + s) * Nz + t];
            float h[Dz];
            float m = 0.f;
            #pragma unroll
            for (int i = 0; i < Dz; i++) { h[i] = a * sWs[i] + sbs[i]; m += h[i]; }
            m *= (1.0f / Dz);
            float var = 0.f;
            #pragma unroll
            for (int i = 0; i < Dz; i++) { float d = h[i] - m; var += d * d; }
            var *= (1.0f / Dz);
            float rs = rsqrtf(var + 1e-5f);
            #pragma unroll
            for (int i = 0; i < Dz; i++)
                zs[t][i] = (h[i] - m) * rs * g1s[i] + bl1s[i];
        }
        __syncthreads();

        for (int o = t; o < 3 * Nz * Dz; o += 128) {
            int mat = o >> 9;
            int r = o & 511;
            int n = r >> 5, d = r & 31;
            const float* W = Ws[mat];
            float acc = 0.f;
            #pragma unroll
            for (int i = 0; i < Dz; i++) acc += zs[n][i] * W[i * Dz + d];
            float* dst = (mat == 0) ? g_q : ((mat == 1) ? g_k : g_v);
            dst[((b * Nz + n) * Sz + off + ti) * Dz + d] = acc;   // compacted
        }
        __syncthreads();
    }
}

// ---------------- kernel D: attention (lane = one head of one query) ---------
// grid = pe*Nz = 1024; block 256 (64 queries x 4 head-lanes); smem key tiles.
// Single-pass softmax referenced to background logit l0; compacted k/v.
__global__ __launch_bounds__(256) void attn_kernel() {
    int blk = blockIdx.x;          // pe*16 + n
    int n = blk & 15;
    int pe = blk >> 4;
    int b = pe / Ez, e = pe % Ez;
    int cnt = g_counts[pe];
    if (cnt == 0) return;
    int off = g_offs[pe];
    long base = (long)(b * Nz + n) * Sz + off;

    __shared__ float ks[64 * Dz];       // 8KB key tile
    __shared__ float vs[64 * Dz];       // 8KB value tile
    __shared__ float k0s[Dz], v0s[Dz];

    int t = threadIdx.x;
    if (t < Dz) {
        k0s[t] = g_k0[e * Dz + t];
        v0s[t] = g_v0[e * Dz + t];
    }
    __syncthreads();

    const float scale = 0.35355339059327373f;   // 1/sqrt(8)
    float fnbg = (float)(Sz - cnt);

    int lq = t >> 2;        // query slot within pass (0..63)
    int hh = t & 3;         // head owned by this lane
    int row = t >> 2;       // tile-load row (0..63)
    int q4  = t & 3;        // tile-load quarter
    int npass = (cnt + 63) >> 6;

    for (int p = 0; p < npass; p++) {
        int qi = p * 64 + lq;
        bool active = qi < cnt;
        int qc = active ? qi : cnt - 1;

        // this lane's 8-dim query slice (one head)
        float qv[8];
        {
            const float4* qg = (const float4*)(g_q + (base + qc) * Dz + hh * 8);
            float4 q0 = __ldg(qg), q1 = __ldg(qg + 1);
            qv[0]=q0.x; qv[1]=q0.y; qv[2]=q0.z; qv[3]=q0.w;
            qv[4]=q1.x; qv[5]=q1.y; qv[6]=q1.z; qv[7]=q1.w;
        }

        float l0 = 0.f;
        #pragma unroll
        for (int i = 0; i < 8; i++) l0 += qv[i] * k0s[hh * 8 + i];
        l0 *= scale;

        float den = fnbg;                       // nbg * exp(l0-l0)
        float o[8];
        #pragma unroll
        for (int i = 0; i < 8; i++) o[i] = fnbg * v0s[hh * 8 + i];

        for (int t0 = 0; t0 < cnt; t0 += 64) {
            __syncthreads();
            {   // cooperative tile load: 256 thr x (8 k-floats + 8 v-floats)
                int gr = min(t0 + row, cnt - 1);
                const float4* kg = (const float4*)(g_k + (base + gr) * Dz + q4 * 8);
                const float4* vg = (const float4*)(g_v + (base + gr) * Dz + q4 * 8);
                float4 ka = __ldg(kg),  kb2 = __ldg(kg + 1);
                float4 va = __ldg(vg),  vb2 = __ldg(vg + 1);
                float4* kd = (float4*)(ks + row * Dz + q4 * 8);
                float4* vd = (float4*)(vs + row * Dz + q4 * 8);
                kd[0] = ka;  kd[1] = kb2;
                vd[0] = va;  vd[1] = vb2;
            }
            __syncthreads();

            int jmax = min(64, cnt - t0);
            #pragma unroll 2
            for (int j = 0; j < jmax; j++) {
                const float4* kr = (const float4*)(ks + j * Dz + hh * 8);
                float4 a = kr[0], c = kr[1];
                float l = qv[0]*a.x + qv[1]*a.y + qv[2]*a.z + qv[3]*a.w
                        + qv[4]*c.x + qv[5]*c.y + qv[6]*c.z + qv[7]*c.w;
                float w = __expf(l * scale - l0);
                den += w;
                const float4* vr = (const float4*)(vs + j * Dz + hh * 8);
                float4 va = vr[0], vc = vr[1];
                o[0] += w * va.x; o[1] += w * va.y;
                o[2] += w * va.z; o[3] += w * va.w;
                o[4] += w * vc.x; o[5] += w * vc.y;
                o[6] += w * vc.z; o[7] += w * vc.w;
            }
        }

        if (active) {
            long gpos = (long)b * Sz + off + qi;    // compacted token index
            float inv = 1.0f / den;
            float4* dst = (float4*)(g_attn + (gpos * Nz + n) * Dz + hh * 8);
            dst[0] = make_float4(o[0]*inv, o[1]*inv, o[2]*inv, o[3]*inv);
            dst[1] = make_float4(o[4]*inv, o[5]*inv, o[6]*inv, o[7]*inv);
        }
    }
}

// ---------------- kernel E1: Wo + LN2 -> z2, h1(+b2) -------------------------
// grid = (b,e)*16 tiles; 128 thr (4 warps x 4 channels); lane = dim
__global__ __launch_bounds__(128, 6) void tail1_kernel(
        const float* __restrict__ sW,  const float* __restrict__ sb,
        const float* __restrict__ Wo,  const float* __restrict__ ln2_g,
        const float* __restrict__ ln2_b, const float* __restrict__ b2) {
    int blk = blockIdx.x;
    int pe = blk >> 4, tile = blk & 15;
    int b = pe / Ez, e = pe % Ez;
    int cnt = g_counts[pe];
    if (cnt == 0) return;
    int off = g_offs[pe];
    int t = threadIdx.x, warp = t >> 5, lane = t & 31;

    __shared__ float att_s[4][4][Dz];

    float wo[Dz];
    #pragma unroll
    for (int i = 0; i < Dz; i++)
        wo[i] = __ldg(&Wo[e * Dz * Dz + i * Dz + lane]);

    const float sWl  = __ldg(&sW[lane]);
    const float sbl  = __ldg(&sb[lane]);
    const float g2l  = __ldg(&ln2_g[e * Dz + lane]);
    const float bl2l = __ldg(&ln2_b[e * Dz + lane]);
    const float b2l  = __ldg(&b2[e * Dz + lane]);

    const int* lst = &g_lists[pe * Sz];
    int n0 = warp * 4;

    for (int ti = tile; ti < cnt; ti += 16) {
        int s = lst[ti];
        long gpos = (long)b * Sz + off + ti;

        #pragma unroll
        for (int ch = 0; ch < 4; ch++)
            att_s[warp][ch][lane] =
                g_attn[(gpos * Nz + n0 + ch) * Dz + lane];
        __syncwarp();

        #pragma unroll
        for (int ch = 0; ch < 4; ch++) {
            float xv = __ldg(&g_xns[((long)b * Sz + s) * Nz + n0 + ch]);
            float h1 = xv * sWl + sbl;
            const float4* ap = (const float4*)att_s[warp][ch];
            #pragma unroll
            for (int j4 = 0; j4 < 8; j4++) {
                float4 a = ap[j4];
                h1 += a.x * wo[j4 * 4 + 0] + a.y * wo[j4 * 4 + 1]
                    + a.z * wo[j4 * 4 + 2] + a.w * wo[j4 * 4 + 3];
            }
            float mu = h1;
            #pragma unroll
            for (int o2 = 16; o2 > 0; o2 >>= 1)
                mu += __shfl_xor_sync(FULLM, mu, o2);
            mu *= (1.0f / Dz);
            float df = h1 - mu;
            float var = df * df;
            #pragma unroll
            for (int o2 = 16; o2 > 0; o2 >>= 1)
                var += __shfl_xor_sync(FULLM, var, o2);
            var *= (1.0f / Dz);
            float z = df * rsqrtf(var + 1e-5f) * g2l + bl2l;
            g_z2[(gpos * Nz + n0 + ch) * Dz + lane] = z;
            g_h1[(gpos * Nz + n0 + ch) * Dz + lane] = h1 + b2l;
        }
        __syncwarp();
    }
}

// ---------------- kernel E2: FFN layer 1 -> f = relu(z2@W1 + b1) -------------
// lane = 2 f-columns (lane, lane+32)
__global__ __launch_bounds__(128, 5) void tail2_kernel(
        const float* __restrict__ W1, const float* __restrict__ b1) {
    int blk = blockIdx.x;
    int pe = blk >> 4, tile = blk & 15;
    int b = pe / Ez, e = pe % Ez;
    int cnt = g_counts[pe];
    if (cnt == 0) return;
    int off = g_offs[pe];
    int t = threadIdx.x, warp = t >> 5, lane = t & 31;

    __shared__ float z2_s[4][4][Dz];

    float w1a[Dz], w1b[Dz];
    #pragma unroll
    for (int i = 0; i < Dz; i++) {
        w1a[i] = __ldg(&W1[e * Dz * DFFz + i * DFFz + lane]);
        w1b[i] = __ldg(&W1[e * Dz * DFFz + i * DFFz + 32 + lane]);
    }
    const float b1a = __ldg(&b1[e * DFFz + lane]);
    const float b1b = __ldg(&b1[e * DFFz + 32 + lane]);

    int n0 = warp * 4;
    for (int ti = tile; ti < cnt; ti += 16) {
        long gpos = (long)b * Sz + off + ti;
        #pragma unroll
        for (int ch = 0; ch < 4; ch++)
            z2_s[warp][ch][lane] = g_z2[(gpos * Nz + n0 + ch) * Dz + lane];
        __syncwarp();

        #pragma unroll
        for (int ch = 0; ch < 4; ch++) {
            float f0 = b1a, f1 = b1b;
            const float4* zp = (const float4*)z2_s[warp][ch];
            #pragma unroll
            for (int i4 = 0; i4 < 8; i4++) {
                float4 z = zp[i4];
                f0 += z.x * w1a[i4*4+0] + z.y * w1a[i4*4+1]
                    + z.z * w1a[i4*4+2] + z.w * w1a[i4*4+3];
                f1 += z.x * w1b[i4*4+0] + z.y * w1b[i4*4+1]
                    + z.z * w1b[i4*4+2] + z.w * w1b[i4*4+3];
            }
            g_f[(gpos * Nz + n0 + ch) * DFFz + lane]      = fmaxf(f0, 0.f);
            g_f[(gpos * Nz + n0 + ch) * DFFz + 32 + lane] = fmaxf(f1, 0.f);
        }
        __syncwarp();
    }
}

// ---------------- kernel E3: FFN layer 2 -> out = h1 + f@W2 ------------------
__global__ __launch_bounds__(128, 5) void tail3_kernel(
        const float* __restrict__ W2, float* __restrict__ out) {
    int blk = blockIdx.x;
    int pe = blk >> 4, tile = blk & 15;
    int b = pe / Ez, e = pe % Ez;
    int cnt = g_counts[pe];
    if (cnt == 0) return;
    int off = g_offs[pe];
    int t = threadIdx.x, warp = t >> 5, lane = t & 31;

    __shared__ float f_s[4][4][DFFz];

    float w2[DFFz];
    #pragma unroll
    for (int j = 0; j < DFFz; j++)
        w2[j] = __ldg(&W2[e * DFFz * Dz + j * Dz + lane]);

    const int* lst = &g_lists[pe * Sz];
    int n0 = warp * 4;

    for (int ti = tile; ti < cnt; ti += 16) {
        int s = lst[ti];
        long gpos = (long)b * Sz + off + ti;
        #pragma unroll
        for (int ch = 0; ch < 4; ch++) {
            f_s[warp][ch][lane]      = g_f[(gpos * Nz + n0 + ch) * DFFz + lane];
            f_s[warp][ch][32 + lane] = g_f[(gpos * Nz + n0 + ch) * DFFz + 32 + lane];
        }
        __syncwarp();

        #pragma unroll
        for (int ch = 0; ch < 4; ch++) {
            float acc = g_h1[(gpos * Nz + n0 + ch) * Dz + lane];
            const float4* fp = (const float4*)f_s[warp][ch];
            #pragma unroll
            for (int j4 = 0; j4 < 16; j4++) {
                float4 f = fp[j4];
                acc += f.x * w2[j4*4+0] + f.y * w2[j4*4+1]
                     + f.z * w2[j4*4+2] + f.w * w2[j4*4+3];
            }
            out[(((long)b * Sz + s) * Nz + n0 + ch) * Dz + lane] = acc;
        }
        __syncwarp();
    }
}

// ---------------- launch ------------------------------------------------------
extern "C" void kernel_launch(void* const* d_in, const int* in_sizes, int n_in,
                              void* d_out, int out_size) {
    const float* x        = (const float*)d_in[0];
    const float* ox       = (const float*)d_in[1];
    const float* start_W  = (const float*)d_in[2];
    const float* start_b  = (const float*)d_in[3];
    const float* Wq       = (const float*)d_in[4];
    const float* Wk       = (const float*)d_in[5];
    const float* Wv       = (const float*)d_in[6];
    const float* Wo       = (const float*)d_in[7];
    const float* ln1_g    = (const float*)d_in[8];
    const float* ln1_b    = (const float*)d_in[9];
    const float* ln2_g    = (const float*)d_in[10];
    const float* ln2_b    = (const float*)d_in[11];
    const float* W1       = (const float*)d_in[12];
    const float* b1       = (const float*)d_in[13];
    const float* W2       = (const float*)d_in[14];
    const float* b2       = (const float*)d_in[15];
    float* out = (float*)d_out;

    preprocess_kernel<<<Bz * Nz, 256>>>(x);
    assign_kernel<<<1, 256>>>(ox, start_b, ln1_g, ln1_b, Wk, Wv);
    qkv_kernel<<<Bz * Ez * 8, 128>>>(start_W, start_b, Wq, Wk, Wv, ln1_g, ln1_b);
    attn_kernel<<<Bz * Ez * Nz, 256>>>();
    tail1_kernel<<<Bz * Ez * 16, 128>>>(start_W, start_b, Wo, ln2_g, ln2_b, b2);
    tail2_kernel<<<Bz * Ez * 16, 128>>>(W1, b1);
    tail3_kernel<<<Bz * Ez * 16, 128>>>(W2, out);
}

// round 11
// speedup vs baseline: 2.1852x; 2.0162x over previous
#include <cuda_runtime.h>
#include <cuda_bf16.h>
#include <math.h>

#define Bz 16
#define Sz 256
#define Cz 17
#define Nz 16
#define Dz 32
#define Ez 4
#define Hz 4
#define DHz 8
#define DFFz 64
#define FULLM 0xffffffffu

// ---------------- scratch (static device memory; no allocations) -------------
__device__ float g_xns[Bz * Sz * Nz];
__device__ int   g_assign[Bz * Sz];
__device__ int   g_lists[Bz * Ez * Sz];
__device__ int   g_counts[Bz * Ez];
__device__ int   g_offs[Bz * Ez];

// LN1 rank-1 factorization artifacts
__device__ float g_PQR[Ez * 3 * 3 * Dz];   // [e][mat q/k/v][basis P/Q/R][d]
__device__ float g_M[Ez * Hz * 9];         // logit bilinear form (scale folded)
__device__ float g_m0[Ez * Hz * 3];        // background logit row (scale folded)
__device__ float g_ABCD[Ez * Hz * 4 * Dz]; // {Pv,Qv,Rv,v0}@Wo per head
__device__ float g_scal[3];                // vW, vb, cv
__device__ float2 g_sc[Bz * Sz * Nz];      // per (compact token, n): (alpha*a, alpha)
__device__ float4 g_c4[Bz * Sz * Nz * Hz]; // attention coeffs per (token,n,h)

__device__ float g_z2[Bz * Sz * Nz * Dz];
__device__ float g_h1[Bz * Sz * Nz * Dz];
__device__ float g_f[Bz * Sz * Nz * DFFz];

// ---------------- kernel A: trend + Fourier season + new_x -------------------
__global__ void preprocess_kernel(const float* __restrict__ x) {
    int blk = blockIdx.x;
    int b = blk / Nz;
    int c = blk % Nz;
    int t = threadIdx.x;

    __shared__ float xs[Sz];
    __shared__ float ctab[Sz], stab[Sz];
    __shared__ float re_s[129], im_s[129], amp_s[129], amp2_s[129];
    __shared__ float keptre[32], keptim[32];
    __shared__ int   keptf[32];
    __shared__ int   nkept_s;
    __shared__ float thr_s;

    if (t == 0) nkept_s = 0;
    xs[t] = x[(b * Sz + t) * Cz + c];
    float ang = (float)t / 128.0f;
    ctab[t] = cospif(ang);
    stab[t] = sinpif(ang);
    __syncthreads();

    if (t < 129) {
        float re = 0.f, im = 0.f;
        for (int u = 0; u < Sz; u++) {
            int idx = (t * u) & 255;
            float xv = xs[u];
            re += xv * ctab[idx];
            im -= xv * stab[idx];
        }
        re_s[t] = re;
        im_s[t] = im;
        float a = (t == 0) ? -1e38f : sqrtf(re * re + im * im);
        amp_s[t] = a;
        amp2_s[t] = a;
    }
    __syncthreads();

    if (t < 32) {
        float thr = 0.f;
        for (int pass = 0; pass < 4; pass++) {
            unsigned long long best = 0ull;
            #pragma unroll
            for (int cc = 0; cc < 5; cc++) {
                int f = cc * 32 + t;
                if (f < 129) {
                    float a = amp2_s[f];
                    if (a > -1e37f) {
                        unsigned long long u =
                            (((unsigned long long)__float_as_uint(a)) << 32) |
                            (unsigned)f;
                        if (u > best) best = u;
                    }
                }
            }
            #pragma unroll
            for (int off = 16; off > 0; off >>= 1) {
                unsigned long long o2 = __shfl_xor_sync(FULLM, best, off);
                if (o2 > best) best = o2;
            }
            int bi = (int)(best & 0xffffffffu);
            thr = __uint_as_float((unsigned)(best >> 32));
            if (t == 0) amp2_s[bi] = -1e38f;
            __syncwarp();
        }
        if (t == 0) thr_s = thr;
    }
    __syncthreads();

    float thr = thr_s;
    if (t < 129 && amp_s[t] >= thr) {
        int p = atomicAdd(&nkept_s, 1);
        if (p < 32) {
            keptf[p] = t;
            keptre[p] = re_s[t];
            keptim[p] = im_s[t];
        }
    }
    __syncthreads();

    float season = 0.f;
    int nk = min(nkept_s, 32);
    for (int j = 0; j < nk; j++) {
        int f = keptf[j];
        float cr = keptre[j], ci = keptim[j];
        int idx = (f * t) & 255;
        if (f == 0)        season += cr;
        else if (f == 128) season += cr * ctab[idx];
        else               season += 2.f * (cr * ctab[idx] - ci * stab[idx]);
    }
    season *= (1.0f / 256.0f);

    float s4 = 0.f, s8 = 0.f, s12 = 0.f;
    #pragma unroll
    for (int i = -1; i <= 2; i++) { int u = min(max(t + i, 0), Sz - 1); s4 += xs[u]; }
    #pragma unroll
    for (int i = -3; i <= 4; i++) { int u = min(max(t + i, 0), Sz - 1); s8 += xs[u]; }
    #pragma unroll
    for (int i = -5; i <= 6; i++) { int u = min(max(t + i, 0), Sz - 1); s12 += xs[u]; }
    float trend = (s4 * 0.25f + s8 * 0.125f + s12 * (1.0f / 12.0f)) * (1.0f / 3.0f);

    g_xns[(b * Sz + t) * Nz + c] = xs[t] + season + trend;
}

// ---------------- kernel B: routing + lists + offsets ------------------------
__global__ void assign_kernel(const float* __restrict__ ox) {
    int t = threadIdx.x;
    __shared__ float red[256];
    __shared__ float smin_s, smax_s;

    float mn = 3.4e38f, mx = -3.4e38f;
    for (int i = t; i < Bz * Sz; i += 256) {
        float s = ox[i * 2 + 1];
        mn = fminf(mn, s);
        mx = fmaxf(mx, s);
    }
    red[t] = mn; __syncthreads();
    for (int o = 128; o > 0; o >>= 1) {
        if (t < o) red[t] = fminf(red[t], red[t + o]);
        __syncthreads();
    }
    if (t == 0) smin_s = red[0];
    __syncthreads();
    red[t] = mx; __syncthreads();
    for (int o = 128; o > 0; o >>= 1) {
        if (t < o) red[t] = fmaxf(red[t], red[t + o]);
        __syncthreads();
    }
    if (t == 0) smax_s = red[0];
    __syncthreads();

    float bmin = smin_s, bmax = smax_s;
    float step = (bmax - bmin) * 0.25f;
    for (int i = t; i < Bz * Sz; i += 256) {
        float s = ox[i * 2 + 1];
        int cntb = 0;
        #pragma unroll
        for (int k = 0; k < 5; k++) {
            float bv = bmin + step * (float)k;
            if (bv <= s) cntb++;
        }
        int a = cntb - 1;
        a = max(0, min(Ez - 1, a));
        g_assign[i] = a;
    }
    __syncthreads();

    int warp = t >> 5, lane = t & 31;
    for (int pe = warp; pe < Bz * Ez; pe += 8) {
        int b = pe / Ez, e = pe % Ez;
        int cnt = 0;
        for (int s0 = 0; s0 < Sz; s0 += 32) {
            int s = s0 + lane;
            int a = g_assign[b * Sz + s];
            unsigned bal = __ballot_sync(FULLM, a == e);
            int pos = cnt + __popc(bal & ((1u << lane) - 1u));
            if (a == e) g_lists[pe * Sz + pos] = s;
            cnt += __popc(bal);
        }
        if (lane == 0) g_counts[pe] = cnt;
    }
    __syncthreads();

    if (t < Bz) {
        int off = 0;
        #pragma unroll
        for (int e = 0; e < Ez; e++) {
            g_offs[t * Ez + e] = off;
            off += g_counts[t * Ez + e];
        }
    }
}

// ---------------- kernel B2: rank-1 LN factorization precompute --------------
// single block, 256 threads
__global__ void precompute_kernel(const float* __restrict__ sW,
                                  const float* __restrict__ sb,
                                  const float* __restrict__ Wq,
                                  const float* __restrict__ Wk,
                                  const float* __restrict__ Wv,
                                  const float* __restrict__ Wo,
                                  const float* __restrict__ ln1_g,
                                  const float* __restrict__ ln1_b) {
    int t = threadIdx.x;
    __shared__ float uWs[Dz], ubs[Dz];
    __shared__ float vbs_sh;

    if (t == 0) {
        float mW = 0.f, mb = 0.f;
        for (int i = 0; i < Dz; i++) { mW += sW[i]; mb += sb[i]; }
        mW *= (1.0f / Dz); mb *= (1.0f / Dz);
        float vW = 0.f, vb = 0.f, cv = 0.f;
        for (int i = 0; i < Dz; i++) {
            float uw = sW[i] - mW, ub = sb[i] - mb;
            uWs[i] = uw; ubs[i] = ub;
            vW += uw * uw; vb += ub * ub; cv += uw * ub;
        }
        vW *= (1.0f / Dz); vb *= (1.0f / Dz); cv *= (1.0f / Dz);
        g_scal[0] = vW; g_scal[1] = vb; g_scal[2] = cv;
        vbs_sh = vb;
    }
    __syncthreads();

    // P/Q/R per (e, mat, d)
    if (t < Ez * Dz) {
        int e = t >> 5, d = t & 31;
        #pragma unroll
        for (int m = 0; m < 3; m++) {
            const float* W = ((m == 0) ? Wq : (m == 1) ? Wk : Wv) + e * Dz * Dz;
            float P = 0.f, Q = 0.f, R = 0.f;
            for (int i = 0; i < Dz; i++) {
                float w = W[i * Dz + d];
                float g = ln1_g[e * Dz + i];
                P += uWs[i] * g * w;
                Q += ubs[i] * g * w;
                R += ln1_b[e * Dz + i] * w;
            }
            g_PQR[((e * 3 + m) * 3 + 0) * Dz + d] = P;
            g_PQR[((e * 3 + m) * 3 + 1) * Dz + d] = Q;
            g_PQR[((e * 3 + m) * 3 + 2) * Dz + d] = R;
        }
    }
    __syncthreads();

    const float scale = 0.35355339059327373f;   // 1/sqrt(8)
    float a0 = rsqrtf(vbs_sh + 1e-5f);          // alpha at a=0 (background)

    // M (3x3 bilinear per e,h) and m0 (background row)
    if (t < Ez * Hz) {
        int e = t >> 2, h = t & 3;
        #pragma unroll
        for (int r = 0; r < 3; r++) {
            const float* qb = &g_PQR[((e * 3 + 0) * 3 + r) * Dz + h * 8];
            #pragma unroll
            for (int c = 0; c < 3; c++) {
                const float* kb = &g_PQR[((e * 3 + 1) * 3 + c) * Dz + h * 8];
                float s = 0.f;
                #pragma unroll
                for (int d = 0; d < 8; d++) s += qb[d] * kb[d];
                g_M[(e * Hz + h) * 9 + r * 3 + c] = s * scale;
            }
            const float* Qk = &g_PQR[((e * 3 + 1) * 3 + 1) * Dz + h * 8];
            const float* Rk = &g_PQR[((e * 3 + 1) * 3 + 2) * Dz + h * 8];
            float s0 = 0.f;
            #pragma unroll
            for (int d = 0; d < 8; d++) s0 += qb[d] * (a0 * Qk[d] + Rk[d]);
            g_m0[(e * Hz + h) * 3 + r] = s0 * scale;
        }
    }

    // ABCD = {Pv,Qv,Rv,v0}(head slice) @ Wo  per (e,h,d)
    if (t < Ez * Dz) {
        int e = t >> 5, d = t & 31;
        const float* Pv = &g_PQR[((e * 3 + 2) * 3 + 0) * Dz];
        const float* Qv = &g_PQR[((e * 3 + 2) * 3 + 1) * Dz];
        const float* Rv = &g_PQR[((e * 3 + 2) * 3 + 2) * Dz];
        const float* WoE = Wo + e * Dz * Dz;
        #pragma unroll
        for (int h = 0; h < Hz; h++) {
            float A = 0.f, B = 0.f, C = 0.f, Dv = 0.f;
            #pragma unroll
            for (int i = 0; i < 8; i++) {
                int ii = h * 8 + i;
                float w = WoE[ii * Dz + d];
                A += Pv[ii] * w;
                B += Qv[ii] * w;
                C += Rv[ii] * w;
                Dv += (a0 * Qv[ii] + Rv[ii]) * w;
            }
            g_ABCD[((e * Hz + h) * 4 + 0) * Dz + d] = A;
            g_ABCD[((e * Hz + h) * 4 + 1) * Dz + d] = B;
            g_ABCD[((e * Hz + h) * 4 + 2) * Dz + d] = C;
            g_ABCD[((e * Hz + h) * 4 + 3) * Dz + d] = Dv;
        }
    }
}

// ---------------- kernel C: per-(token,n) scalars (alpha*a, alpha) -----------
// grid = pe = 64 blocks, 256 threads; compacted token order
__global__ void sc_kernel() {
    int pe = blockIdx.x;
    int b = pe / Ez;
    int cnt = g_counts[pe];
    if (cnt == 0) return;
    int off = g_offs[pe];
    int t = threadIdx.x;

    __shared__ int lst_s[Sz];
    for (int i = t; i < cnt; i += 256) lst_s[i] = g_lists[pe * Sz + i];
    __syncthreads();

    float vW = g_scal[0], vb = g_scal[1], cv = g_scal[2];
    for (int i = t; i < cnt * Nz; i += 256) {
        int ti = i >> 4, n = i & 15;
        int s = lst_s[ti];
        float a = g_xns[(b * Sz + s) * Nz + n];
        float al = rsqrtf((a * vW + 2.f * cv) * a + vb + 1e-5f);
        g_sc[((long)(b * Sz + off + ti)) * Nz + n] = make_float2(al * a, al);
    }
}

// ---------------- kernel D: attention via 3x3 bilinear logits ----------------
// grid = pe*Nz = 1024; block 256 (64 queries x 4 head-lanes)
__global__ __launch_bounds__(256) void attn_kernel() {
    int blk = blockIdx.x;
    int n = blk & 15;
    int pe = blk >> 4;
    int b = pe / Ez, e = pe % Ez;
    int cnt = g_counts[pe];
    if (cnt == 0) return;
    int off = g_offs[pe];
    long gbase = (long)b * Sz + off;

    __shared__ float4 yk[Sz * Hz];     // 16KB: y = M_h @ uk per (key,h)
    __shared__ float2 uks[Sz];         // 2KB
    __shared__ float M_s[Hz * 9];
    __shared__ float m0_s[Hz * 3];

    int t = threadIdx.x;
    if (t < Hz * 9)  M_s[t]  = g_M[e * Hz * 9 + t];
    if (t < Hz * 3)  m0_s[t] = g_m0[e * Hz * 3 + t];
    __syncthreads();

    for (int i = t; i < cnt * Hz; i += 256) {
        int j = i >> 2, h = i & 3;
        float2 u = g_sc[(gbase + j) * Nz + n];
        const float* M = &M_s[h * 9];
        float y0 = M[0] * u.x + M[1] * u.y + M[2];
        float y1 = M[3] * u.x + M[4] * u.y + M[5];
        float y2 = M[6] * u.x + M[7] * u.y + M[8];
        yk[j * Hz + h] = make_float4(y0, y1, y2, 0.f);
        if (h == 0) uks[j] = u;
    }
    __syncthreads();

    int lq = t >> 2, hh = t & 3;
    float fnbg = (float)(Sz - cnt);
    int npass = (cnt + 63) >> 6;

    for (int p = 0; p < npass; p++) {
        int qi = p * 64 + lq;
        bool active = qi < cnt;
        int qc = active ? qi : cnt - 1;

        float2 uq = g_sc[(gbase + qc) * Nz + n];
        const float* m0 = &m0_s[hh * 3];
        float l0 = m0[0] * uq.x + m0[1] * uq.y + m0[2];

        float T0 = 0.f, T1 = 0.f, T2 = 0.f;
        #pragma unroll 4
        for (int j = 0; j < cnt; j++) {
            float4 y = yk[j * Hz + hh];
            float l = uq.x * y.x + uq.y * y.y + y.z;
            float w = __expf(l - l0);
            float2 uk = uks[j];
            T0 += w * uk.x;
            T1 += w * uk.y;
            T2 += w;
        }
        float inv = 1.0f / (T2 + fnbg);
        if (active) {
            g_c4[((gbase + qi) * Nz + n) * Hz + hh] =
                make_float4(T0 * inv, T1 * inv, T2 * inv, fnbg * inv);
        }
    }
}

// ---------------- kernel E1: h1 from coeffs + LN2 -> z2, h1(+b2) -------------
// grid = (b,e)*16 tiles; 128 thr (4 warps x 4 channels); lane = dim
__global__ __launch_bounds__(128, 6) void tail1_kernel(
        const float* __restrict__ sW,  const float* __restrict__ sb,
        const float* __restrict__ ln2_g, const float* __restrict__ ln2_b,
        const float* __restrict__ b2) {
    int blk = blockIdx.x;
    int pe = blk >> 4, tile = blk & 15;
    int b = pe / Ez, e = pe % Ez;
    int cnt = g_counts[pe];
    if (cnt == 0) return;
    int off = g_offs[pe];
    int t = threadIdx.x, warp = t >> 5, lane = t & 31;

    float abcd[16];
    #pragma unroll
    for (int h = 0; h < Hz; h++)
        #pragma unroll
        for (int r = 0; r < 4; r++)
            abcd[h * 4 + r] = __ldg(&g_ABCD[((e * Hz + h) * 4 + r) * Dz + lane]);

    const float sWl  = __ldg(&sW[lane]);
    const float sbl  = __ldg(&sb[lane]);
    const float g2l  = __ldg(&ln2_g[e * Dz + lane]);
    const float bl2l = __ldg(&ln2_b[e * Dz + lane]);
    const float b2l  = __ldg(&b2[e * Dz + lane]);

    const int* lst = &g_lists[pe * Sz];
    int n0 = warp * 4;

    for (int ti = tile; ti < cnt; ti += 16) {
        int s = lst[ti];
        long gpos = (long)b * Sz + off + ti;

        #pragma unroll
        for (int ch = 0; ch < 4; ch++) {
            int n = n0 + ch;
            float a = __ldg(&g_xns[((long)b * Sz + s) * Nz + n]);
            float h1 = a * sWl + sbl;
            const float4* cp = &g_c4[(gpos * Nz + n) * Hz];
            #pragma unroll
            for (int h = 0; h < Hz; h++) {
                float4 c = __ldg(cp + h);       // broadcast across lanes
                h1 += c.x * abcd[h * 4 + 0] + c.y * abcd[h * 4 + 1]
                    + c.z * abcd[h * 4 + 2] + c.w * abcd[h * 4 + 3];
            }
            float mu = h1;
            #pragma unroll
            for (int o2 = 16; o2 > 0; o2 >>= 1)
                mu += __shfl_xor_sync(FULLM, mu, o2);
            mu *= (1.0f / Dz);
            float df = h1 - mu;
            float var = df * df;
            #pragma unroll
            for (int o2 = 16; o2 > 0; o2 >>= 1)
                var += __shfl_xor_sync(FULLM, var, o2);
            var *= (1.0f / Dz);
            float z = df * rsqrtf(var + 1e-5f) * g2l + bl2l;
            g_z2[(gpos * Nz + n) * Dz + lane] = z;
            g_h1[(gpos * Nz + n) * Dz + lane] = h1 + b2l;
        }
    }
}

// ---------------- kernel E2: FFN layer 1 -> f = relu(z2@W1 + b1) -------------
__global__ __launch_bounds__(128, 5) void tail2_kernel(
        const float* __restrict__ W1, const float* __restrict__ b1) {
    int blk = blockIdx.x;
    int pe = blk >> 4, tile = blk & 15;
    int b = pe / Ez, e = pe % Ez;
    int cnt = g_counts[pe];
    if (cnt == 0) return;
    int off = g_offs[pe];
    int t = threadIdx.x, warp = t >> 5, lane = t & 31;

    __shared__ float z2_s[4][4][Dz];

    float w1a[Dz], w1b[Dz];
    #pragma unroll
    for (int i = 0; i < Dz; i++) {
        w1a[i] = __ldg(&W1[e * Dz * DFFz + i * DFFz + lane]);
        w1b[i] = __ldg(&W1[e * Dz * DFFz + i * DFFz + 32 + lane]);
    }
    const float b1a = __ldg(&b1[e * DFFz + lane]);
    const float b1b = __ldg(&b1[e * DFFz + 32 + lane]);

    int n0 = warp * 4;
    for (int ti = tile; ti < cnt; ti += 16) {
        long gpos = (long)b * Sz + off + ti;
        #pragma unroll
        for (int ch = 0; ch < 4; ch++)
            z2_s[warp][ch][lane] = g_z2[(gpos * Nz + n0 + ch) * Dz + lane];
        __syncwarp();

        #pragma unroll
        for (int ch = 0; ch < 4; ch++) {
            float f0 = b1a, f1 = b1b;
            const float4* zp = (const float4*)z2_s[warp][ch];
            #pragma unroll
            for (int i4 = 0; i4 < 8; i4++) {
                float4 z = zp[i4];
                f0 += z.x * w1a[i4*4+0] + z.y * w1a[i4*4+1]
                    + z.z * w1a[i4*4+2] + z.w * w1a[i4*4+3];
                f1 += z.x * w1b[i4*4+0] + z.y * w1b[i4*4+1]
                    + z.z * w1b[i4*4+2] + z.w * w1b[i4*4+3];
            }
            g_f[(gpos * Nz + n0 + ch) * DFFz + lane]      = fmaxf(f0, 0.f);
            g_f[(gpos * Nz + n0 + ch) * DFFz + 32 + lane] = fmaxf(f1, 0.f);
        }
        __syncwarp();
    }
}

// ---------------- kernel E3: FFN layer 2 -> out = h1 + f@W2 ------------------
__global__ __launch_bounds__(128, 5) void tail3_kernel(
        const float* __restrict__ W2, float* __restrict__ out) {
    int blk = blockIdx.x;
    int pe = blk >> 4, tile = blk & 15;
    int b = pe / Ez, e = pe % Ez;
    int cnt = g_counts[pe];
    if (cnt == 0) return;
    int off = g_offs[pe];
    int t = threadIdx.x, warp = t >> 5, lane = t & 31;

    __shared__ float f_s[4][4][DFFz];

    float w2[DFFz];
    #pragma unroll
    for (int j = 0; j < DFFz; j++)
        w2[j] = __ldg(&W2[e * DFFz * Dz + j * Dz + lane]);

    const int* lst = &g_lists[pe * Sz];
    int n0 = warp * 4;

    for (int ti = tile; ti < cnt; ti += 16) {
        int s = lst[ti];
        long gpos = (long)b * Sz + off + ti;
        #pragma unroll
        for (int ch = 0; ch < 4; ch++) {
            f_s[warp][ch][lane]      = g_f[(gpos * Nz + n0 + ch) * DFFz + lane];
            f_s[warp][ch][32 + lane] = g_f[(gpos * Nz + n0 + ch) * DFFz + 32 + lane];
        }
        __syncwarp();

        #pragma unroll
        for (int ch = 0; ch < 4; ch++) {
            float acc = g_h1[(gpos * Nz + n0 + ch) * Dz + lane];
            const float4* fp = (const float4*)f_s[warp][ch];
            #pragma unroll
            for (int j4 = 0; j4 < 16; j4++) {
                float4 f = fp[j4];
                acc += f.x * w2[j4*4+0] + f.y * w2[j4*4+1]
                     + f.z * w2[j4*4+2] + f.w * w2[j4*4+3];
            }
            out[(((long)b * Sz + s) * Nz + n0 + ch) * Dz + lane] = acc;
        }
        __syncwarp();
    }
}

// ---------------- launch ------------------------------------------------------
extern "C" void kernel_launch(void* const* d_in, const int* in_sizes, int n_in,
                              void* d_out, int out_size) {
    const float* x        = (const float*)d_in[0];
    const float* ox       = (const float*)d_in[1];
    const float* start_W  = (const float*)d_in[2];
    const float* start_b  = (const float*)d_in[3];
    const float* Wq       = (const float*)d_in[4];
    const float* Wk       = (const float*)d_in[5];
    const float* Wv       = (const float*)d_in[6];
    const float* Wo       = (const float*)d_in[7];
    const float* ln1_g    = (const float*)d_in[8];
    const float* ln1_b    = (const float*)d_in[9];
    const float* ln2_g    = (const float*)d_in[10];
    const float* ln2_b    = (const float*)d_in[11];
    const float* W1       = (const float*)d_in[12];
    const float* b1       = (const float*)d_in[13];
    const float* W2       = (const float*)d_in[14];
    const float* b2       = (const float*)d_in[15];
    float* out = (float*)d_out;

    preprocess_kernel<<<Bz * Nz, 256>>>(x);
    assign_kernel<<<1, 256>>>(ox);
    precompute_kernel<<<1, 256>>>(start_W, start_b, Wq, Wk, Wv, Wo, ln1_g, ln1_b);
    sc_kernel<<<Bz * Ez, 256>>>();
    attn_kernel<<<Bz * Ez * Nz, 256>>>();
    tail1_kernel<<<Bz * Ez * 16, 128>>>(start_W, start_b, ln2_g, ln2_b, b2);
    tail2_kernel<<<Bz * Ez * 16, 128>>>(W1, b1);
    tail3_kernel<<<Bz * Ez * 16, 128>>>(W2, out);
}

// round 13
// speedup vs baseline: 2.4438x; 1.1183x over previous
#include <cuda_runtime.h>
#include <cuda_bf16.h>
#include <math.h>

#define Bz 16
#define Sz 256
#define Cz 17
#define Nz 16
#define Dz 32
#define Ez 4
#define Hz 4
#define DHz 8
#define DFFz 64
#define FULLM 0xffffffffu

// ---------------- scratch (static device memory; no allocations) -------------
__device__ float g_xns[Bz * Sz * Nz];
__device__ int   g_assign[Bz * Sz];
__device__ int   g_lists[Bz * Ez * Sz];
__device__ int   g_counts[Bz * Ez];
__device__ int   g_offs[Bz * Ez];

// LN1 rank-1 factorization artifacts
__device__ float g_PQR[Ez * 3 * 3 * Dz];   // [e][mat q/k/v][basis P/Q/R][d]
__device__ float g_M[Ez * Hz * 9];         // logit bilinear form (scale folded)
__device__ float g_m0[Ez * Hz * 3];        // background logit row (scale folded)
__device__ float g_ABCD[Ez * Hz * 4 * Dz]; // {Pv,Qv,Rv,v0}@Wo per head
__device__ float g_scal[3];                // vW, vb, cv
__device__ float4 g_c4[Bz * Sz * Nz * Hz]; // attention coeffs per (token,n,h)

__device__ float g_z2[Bz * Sz * Nz * Dz];
__device__ float g_h1[Bz * Sz * Nz * Dz];

// ---------------- kernel A: trend + Fourier season + new_x -------------------
__global__ void preprocess_kernel(const float* __restrict__ x) {
    int blk = blockIdx.x;
    int b = blk / Nz;
    int c = blk % Nz;
    int t = threadIdx.x;

    __shared__ float xs[Sz];
    __shared__ float ctab[Sz], stab[Sz];
    __shared__ float re_s[129], im_s[129], amp_s[129], amp2_s[129];
    __shared__ float keptre[32], keptim[32];
    __shared__ int   keptf[32];
    __shared__ int   nkept_s;
    __shared__ float thr_s;

    if (t == 0) nkept_s = 0;
    xs[t] = x[(b * Sz + t) * Cz + c];
    float ang = (float)t / 128.0f;
    ctab[t] = cospif(ang);
    stab[t] = sinpif(ang);
    __syncthreads();

    if (t < 129) {
        float re = 0.f, im = 0.f;
        for (int u = 0; u < Sz; u++) {
            int idx = (t * u) & 255;
            float xv = xs[u];
            re += xv * ctab[idx];
            im -= xv * stab[idx];
        }
        re_s[t] = re;
        im_s[t] = im;
        float a = (t == 0) ? -1e38f : sqrtf(re * re + im * im);
        amp_s[t] = a;
        amp2_s[t] = a;
    }
    __syncthreads();

    if (t < 32) {
        float thr = 0.f;
        for (int pass = 0; pass < 4; pass++) {
            unsigned long long best = 0ull;
            #pragma unroll
            for (int cc = 0; cc < 5; cc++) {
                int f = cc * 32 + t;
                if (f < 129) {
                    float a = amp2_s[f];
                    if (a > -1e37f) {
                        unsigned long long u =
                            (((unsigned long long)__float_as_uint(a)) << 32) |
                            (unsigned)f;
                        if (u > best) best = u;
                    }
                }
            }
            #pragma unroll
            for (int off = 16; off > 0; off >>= 1) {
                unsigned long long o2 = __shfl_xor_sync(FULLM, best, off);
                if (o2 > best) best = o2;
            }
            int bi = (int)(best & 0xffffffffu);
            thr = __uint_as_float((unsigned)(best >> 32));
            if (t == 0) amp2_s[bi] = -1e38f;
            __syncwarp();
        }
        if (t == 0) thr_s = thr;
    }
    __syncthreads();

    float thr = thr_s;
    if (t < 129 && amp_s[t] >= thr) {
        int p = atomicAdd(&nkept_s, 1);
        if (p < 32) {
            keptf[p] = t;
            keptre[p] = re_s[t];
            keptim[p] = im_s[t];
        }
    }
    __syncthreads();

    float season = 0.f;
    int nk = min(nkept_s, 32);
    for (int j = 0; j < nk; j++) {
        int f = keptf[j];
        float cr = keptre[j], ci = keptim[j];
        int idx = (f * t) & 255;
        if (f == 0)        season += cr;
        else if (f == 128) season += cr * ctab[idx];
        else               season += 2.f * (cr * ctab[idx] - ci * stab[idx]);
    }
    season *= (1.0f / 256.0f);

    float s4 = 0.f, s8 = 0.f, s12 = 0.f;
    #pragma unroll
    for (int i = -1; i <= 2; i++) { int u = min(max(t + i, 0), Sz - 1); s4 += xs[u]; }
    #pragma unroll
    for (int i = -3; i <= 4; i++) { int u = min(max(t + i, 0), Sz - 1); s8 += xs[u]; }
    #pragma unroll
    for (int i = -5; i <= 6; i++) { int u = min(max(t + i, 0), Sz - 1); s12 += xs[u]; }
    float trend = (s4 * 0.25f + s8 * 0.125f + s12 * (1.0f / 12.0f)) * (1.0f / 3.0f);

    g_xns[(b * Sz + t) * Nz + c] = xs[t] + season + trend;
}

// ---------------- kernel B: routing (block 0) + rank-1 precompute (block 1) --
__global__ void route_pre_kernel(const float* __restrict__ ox,
                                 const float* __restrict__ sW,
                                 const float* __restrict__ sb,
                                 const float* __restrict__ Wq,
                                 const float* __restrict__ Wk,
                                 const float* __restrict__ Wv,
                                 const float* __restrict__ Wo,
                                 const float* __restrict__ ln1_g,
                                 const float* __restrict__ ln1_b) {
    int t = threadIdx.x;

    if (blockIdx.x == 0) {
        // ---------------- routing ----------------
        __shared__ float red[256];
        __shared__ float smin_s, smax_s;

        float mn = 3.4e38f, mx = -3.4e38f;
        for (int i = t; i < Bz * Sz; i += 256) {
            float s = ox[i * 2 + 1];
            mn = fminf(mn, s);
            mx = fmaxf(mx, s);
        }
        red[t] = mn; __syncthreads();
        for (int o = 128; o > 0; o >>= 1) {
            if (t < o) red[t] = fminf(red[t], red[t + o]);
            __syncthreads();
        }
        if (t == 0) smin_s = red[0];
        __syncthreads();
        red[t] = mx; __syncthreads();
        for (int o = 128; o > 0; o >>= 1) {
            if (t < o) red[t] = fmaxf(red[t], red[t + o]);
            __syncthreads();
        }
        if (t == 0) smax_s = red[0];
        __syncthreads();

        float bmin = smin_s, bmax = smax_s;
        float step = (bmax - bmin) * 0.25f;
        for (int i = t; i < Bz * Sz; i += 256) {
            float s = ox[i * 2 + 1];
            int cntb = 0;
            #pragma unroll
            for (int k = 0; k < 5; k++) {
                float bv = bmin + step * (float)k;
                if (bv <= s) cntb++;
            }
            int a = cntb - 1;
            a = max(0, min(Ez - 1, a));
            g_assign[i] = a;
        }
        __syncthreads();

        int warp = t >> 5, lane = t & 31;
        for (int pe = warp; pe < Bz * Ez; pe += 8) {
            int b = pe / Ez, e = pe % Ez;
            int cnt = 0;
            for (int s0 = 0; s0 < Sz; s0 += 32) {
                int s = s0 + lane;
                int a = g_assign[b * Sz + s];
                unsigned bal = __ballot_sync(FULLM, a == e);
                int pos = cnt + __popc(bal & ((1u << lane) - 1u));
                if (a == e) g_lists[pe * Sz + pos] = s;
                cnt += __popc(bal);
            }
            if (lane == 0) g_counts[pe] = cnt;
        }
        __syncthreads();

        if (t < Bz) {
            int off = 0;
            #pragma unroll
            for (int e = 0; e < Ez; e++) {
                g_offs[t * Ez + e] = off;
                off += g_counts[t * Ez + e];
            }
        }
    } else {
        // ---------------- rank-1 LN factorization precompute ----------------
        __shared__ float uWs[Dz], ubs[Dz];
        __shared__ float vbs_sh;

        if (t == 0) {
            float mW = 0.f, mb = 0.f;
            for (int i = 0; i < Dz; i++) { mW += sW[i]; mb += sb[i]; }
            mW *= (1.0f / Dz); mb *= (1.0f / Dz);
            float vW = 0.f, vb = 0.f, cv = 0.f;
            for (int i = 0; i < Dz; i++) {
                float uw = sW[i] - mW, ub = sb[i] - mb;
                uWs[i] = uw; ubs[i] = ub;
                vW += uw * uw; vb += ub * ub; cv += uw * ub;
            }
            vW *= (1.0f / Dz); vb *= (1.0f / Dz); cv *= (1.0f / Dz);
            g_scal[0] = vW; g_scal[1] = vb; g_scal[2] = cv;
            vbs_sh = vb;
        }
        __syncthreads();

        if (t < Ez * Dz) {
            int e = t >> 5, d = t & 31;
            #pragma unroll
            for (int m = 0; m < 3; m++) {
                const float* W = ((m == 0) ? Wq : (m == 1) ? Wk : Wv) + e * Dz * Dz;
                float P = 0.f, Q = 0.f, R = 0.f;
                for (int i = 0; i < Dz; i++) {
                    float w = W[i * Dz + d];
                    float g = ln1_g[e * Dz + i];
                    P += uWs[i] * g * w;
                    Q += ubs[i] * g * w;
                    R += ln1_b[e * Dz + i] * w;
                }
                g_PQR[((e * 3 + m) * 3 + 0) * Dz + d] = P;
                g_PQR[((e * 3 + m) * 3 + 1) * Dz + d] = Q;
                g_PQR[((e * 3 + m) * 3 + 2) * Dz + d] = R;
            }
        }
        __syncthreads();

        const float scale = 0.35355339059327373f;   // 1/sqrt(8)
        float a0 = rsqrtf(vbs_sh + 1e-5f);          // alpha at a=0 (background)

        if (t < Ez * Hz) {
            int e = t >> 2, h = t & 3;
            #pragma unroll
            for (int r = 0; r < 3; r++) {
                const float* qb = &g_PQR[((e * 3 + 0) * 3 + r) * Dz + h * 8];
                #pragma unroll
                for (int c = 0; c < 3; c++) {
                    const float* kb = &g_PQR[((e * 3 + 1) * 3 + c) * Dz + h * 8];
                    float s = 0.f;
                    #pragma unroll
                    for (int d = 0; d < 8; d++) s += qb[d] * kb[d];
                    g_M[(e * Hz + h) * 9 + r * 3 + c] = s * scale;
                }
                const float* Qk = &g_PQR[((e * 3 + 1) * 3 + 1) * Dz + h * 8];
                const float* Rk = &g_PQR[((e * 3 + 1) * 3 + 2) * Dz + h * 8];
                float s0 = 0.f;
                #pragma unroll
                for (int d = 0; d < 8; d++) s0 += qb[d] * (a0 * Qk[d] + Rk[d]);
                g_m0[(e * Hz + h) * 3 + r] = s0 * scale;
            }
        }

        if (t < Ez * Dz) {
            int e = t >> 5, d = t & 31;
            const float* Pv = &g_PQR[((e * 3 + 2) * 3 + 0) * Dz];
            const float* Qv = &g_PQR[((e * 3 + 2) * 3 + 1) * Dz];
            const float* Rv = &g_PQR[((e * 3 + 2) * 3 + 2) * Dz];
            const float* WoE = Wo + e * Dz * Dz;
            #pragma unroll
            for (int h = 0; h < Hz; h++) {
                float A = 0.f, B = 0.f, C = 0.f, Dv = 0.f;
                #pragma unroll
                for (int i = 0; i < 8; i++) {
                    int ii = h * 8 + i;
                    float w = WoE[ii * Dz + d];
                    A += Pv[ii] * w;
                    B += Qv[ii] * w;
                    C += Rv[ii] * w;
                    Dv += (a0 * Qv[ii] + Rv[ii]) * w;
                }
                g_ABCD[((e * Hz + h) * 4 + 0) * Dz + d] = A;
                g_ABCD[((e * Hz + h) * 4 + 1) * Dz + d] = B;
                g_ABCD[((e * Hz + h) * 4 + 2) * Dz + d] = C;
                g_ABCD[((e * Hz + h) * 4 + 3) * Dz + d] = Dv;
            }
        }
    }
}

// ---------------- kernel D: attention via 3x3 bilinear logits (sc fused) -----
// grid = pe*Nz = 1024; block 256 (64 queries x 4 head-lanes)
__global__ __launch_bounds__(256) void attn_kernel() {
    int blk = blockIdx.x;
    int n = blk & 15;
    int pe = blk >> 4;
    int b = pe / Ez, e = pe % Ez;
    int cnt = g_counts[pe];
    if (cnt == 0) return;
    int off = g_offs[pe];
    long gbase = (long)b * Sz + off;

    __shared__ int lst_s[Sz];
    __shared__ float4 yk[Sz * Hz];     // 16KB: y = M_h @ uk per (key,h)
    __shared__ float2 uks[Sz];         // 2KB
    __shared__ float M_s[Hz * 9];
    __shared__ float m0_s[Hz * 3];

    int t = threadIdx.x;
    if (t < Hz * 9)  M_s[t]  = g_M[e * Hz * 9 + t];
    if (t < Hz * 3)  m0_s[t] = g_m0[e * Hz * 3 + t];
    for (int i = t; i < cnt; i += 256) lst_s[i] = g_lists[pe * Sz + i];
    __syncthreads();

    // per-key scalars (alpha*a, alpha), fused (formerly sc_kernel)
    float vW = g_scal[0], vb = g_scal[1], cv = g_scal[2];
    for (int i = t; i < cnt; i += 256) {
        float a = g_xns[(b * Sz + lst_s[i]) * Nz + n];
        float al = rsqrtf((a * vW + 2.f * cv) * a + vb + 1e-5f);
        uks[i] = make_float2(al * a, al);
    }
    __syncthreads();

    for (int i = t; i < cnt * Hz; i += 256) {
        int j = i >> 2, h = i & 3;
        float2 u = uks[j];
        const float* M = &M_s[h * 9];
        float y0 = M[0] * u.x + M[1] * u.y + M[2];
        float y1 = M[3] * u.x + M[4] * u.y + M[5];
        float y2 = M[6] * u.x + M[7] * u.y + M[8];
        yk[j * Hz + h] = make_float4(y0, y1, y2, 0.f);
    }
    __syncthreads();

    int lq = t >> 2, hh = t & 3;
    float fnbg = (float)(Sz - cnt);
    int npass = (cnt + 63) >> 6;

    for (int p = 0; p < npass; p++) {
        int qi = p * 64 + lq;
        bool active = qi < cnt;
        int qc = active ? qi : cnt - 1;

        float2 uq = uks[qc];
        const float* m0 = &m0_s[hh * 3];
        float l0 = m0[0] * uq.x + m0[1] * uq.y + m0[2];

        float T0 = 0.f, T1 = 0.f, T2 = 0.f;
        #pragma unroll 4
        for (int j = 0; j < cnt; j++) {
            float4 y = yk[j * Hz + hh];
            float l = uq.x * y.x + uq.y * y.y + y.z;
            float w = __expf(l - l0);
            float2 uk = uks[j];
            T0 += w * uk.x;
            T1 += w * uk.y;
            T2 += w;
        }
        float inv = 1.0f / (T2 + fnbg);
        if (active) {
            g_c4[((gbase + qi) * Nz + n) * Hz + hh] =
                make_float4(T0 * inv, T1 * inv, T2 * inv, fnbg * inv);
        }
    }
}

// ---------------- kernel E1: h1 from coeffs + LN2 -> z2, h1(+b2) -------------
// grid = (b,e)*16 tiles; 128 thr (4 warps x 4 channels); lane = dim
__global__ __launch_bounds__(128, 6) void tail1_kernel(
        const float* __restrict__ sW,  const float* __restrict__ sb,
        const float* __restrict__ ln2_g, const float* __restrict__ ln2_b,
        const float* __restrict__ b2) {
    int blk = blockIdx.x;
    int pe = blk >> 4, tile = blk & 15;
    int b = pe / Ez, e = pe % Ez;
    int cnt = g_counts[pe];
    if (cnt == 0) return;
    int off = g_offs[pe];
    int t = threadIdx.x, warp = t >> 5, lane = t & 31;

    float abcd[16];
    #pragma unroll
    for (int h = 0; h < Hz; h++)
        #pragma unroll
        for (int r = 0; r < 4; r++)
            abcd[h * 4 + r] = __ldg(&g_ABCD[((e * Hz + h) * 4 + r) * Dz + lane]);

    const float sWl  = __ldg(&sW[lane]);
    const float sbl  = __ldg(&sb[lane]);
    const float g2l  = __ldg(&ln2_g[e * Dz + lane]);
    const float bl2l = __ldg(&ln2_b[e * Dz + lane]);
    const float b2l  = __ldg(&b2[e * Dz + lane]);

    const int* lst = &g_lists[pe * Sz];
    int n0 = warp * 4;

    for (int ti = tile; ti < cnt; ti += 16) {
        int s = lst[ti];
        long gpos = (long)b * Sz + off + ti;

        #pragma unroll
        for (int ch = 0; ch < 4; ch++) {
            int n = n0 + ch;
            float a = __ldg(&g_xns[((long)b * Sz + s) * Nz + n]);
            float h1 = a * sWl + sbl;
            const float4* cp = &g_c4[(gpos * Nz + n) * Hz];
            #pragma unroll
            for (int h = 0; h < Hz; h++) {
                float4 c = __ldg(cp + h);       // broadcast across lanes
                h1 += c.x * abcd[h * 4 + 0] + c.y * abcd[h * 4 + 1]
                    + c.z * abcd[h * 4 + 2] + c.w * abcd[h * 4 + 3];
            }
            float mu = h1;
            #pragma unroll
            for (int o2 = 16; o2 > 0; o2 >>= 1)
                mu += __shfl_xor_sync(FULLM, mu, o2);
            mu *= (1.0f / Dz);
            float df = h1 - mu;
            float var = df * df;
            #pragma unroll
            for (int o2 = 16; o2 > 0; o2 >>= 1)
                var += __shfl_xor_sync(FULLM, var, o2);
            var *= (1.0f / Dz);
            float z = df * rsqrtf(var + 1e-5f) * g2l + bl2l;
            g_z2[(gpos * Nz + n) * Dz + lane] = z;
            g_h1[(gpos * Nz + n) * Dz + lane] = h1 + b2l;
        }
    }
}

// ---------------- kernel E2: fused FFN (f in smem, no global round trip) -----
// grid = (b,e)*16 tiles; 128 thr (4 warps x 4 channels); lane = dim / 2 f-cols
__global__ __launch_bounds__(128, 3) void tail23_kernel(
        const float* __restrict__ W1, const float* __restrict__ b1,
        const float* __restrict__ W2, float* __restrict__ out) {
    int blk = blockIdx.x;
    int pe = blk >> 4, tile = blk & 15;
    int b = pe / Ez, e = pe % Ez;
    int cnt = g_counts[pe];
    if (cnt == 0) return;
    int off = g_offs[pe];
    int t = threadIdx.x, warp = t >> 5, lane = t & 31;

    __shared__ float z2_s[4][4][Dz];
    __shared__ float f_s[4][4][DFFz];

    float w1a[Dz], w1b[Dz], w2[DFFz];
    #pragma unroll
    for (int i = 0; i < Dz; i++) {
        w1a[i] = __ldg(&W1[e * Dz * DFFz + i * DFFz + lane]);
        w1b[i] = __ldg(&W1[e * Dz * DFFz + i * DFFz + 32 + lane]);
    }
    #pragma unroll
    for (int j = 0; j < DFFz; j++)
        w2[j] = __ldg(&W2[e * DFFz * Dz + j * Dz + lane]);

    const float b1a = __ldg(&b1[e * DFFz + lane]);
    const float b1b = __ldg(&b1[e * DFFz + 32 + lane]);

    const int* lst = &g_lists[pe * Sz];
    int n0 = warp * 4;

    for (int ti = tile; ti < cnt; ti += 16) {
        int s = lst[ti];
        long gpos = (long)b * Sz + off + ti;

        #pragma unroll
        for (int ch = 0; ch < 4; ch++)
            z2_s[warp][ch][lane] = g_z2[(gpos * Nz + n0 + ch) * Dz + lane];
        __syncwarp();

        // FFN layer 1: f = relu(z2 @ W1 + b1)
        #pragma unroll
        for (int ch = 0; ch < 4; ch++) {
            float f0 = b1a, f1 = b1b;
            const float4* zp = (const float4*)z2_s[warp][ch];
            #pragma unroll
            for (int i4 = 0; i4 < 8; i4++) {
                float4 z = zp[i4];
                f0 += z.x * w1a[i4*4+0] + z.y * w1a[i4*4+1]
                    + z.z * w1a[i4*4+2] + z.w * w1a[i4*4+3];
                f1 += z.x * w1b[i4*4+0] + z.y * w1b[i4*4+1]
                    + z.z * w1b[i4*4+2] + z.w * w1b[i4*4+3];
            }
            f_s[warp][ch][lane]      = fmaxf(f0, 0.f);
            f_s[warp][ch][32 + lane] = fmaxf(f1, 0.f);
        }
        __syncwarp();

        // FFN layer 2: out = h1 + f @ W2
        #pragma unroll
        for (int ch = 0; ch < 4; ch++) {
            float acc = g_h1[(gpos * Nz + n0 + ch) * Dz + lane];
            const float4* fp = (const float4*)f_s[warp][ch];
            #pragma unroll
            for (int j4 = 0; j4 < 16; j4++) {
                float4 f = fp[j4];
                acc += f.x * w2[j4*4+0] + f.y * w2[j4*4+1]
                     + f.z * w2[j4*4+2] + f.w * w2[j4*4+3];
            }
            out[(((long)b * Sz + s) * Nz + n0 + ch) * Dz + lane] = acc;
        }
        __syncwarp();
    }
}

// ---------------- launch ------------------------------------------------------
extern "C" void kernel_launch(void* const* d_in, const int* in_sizes, int n_in,
                              void* d_out, int out_size) {
    const float* x        = (const float*)d_in[0];
    const float* ox       = (const float*)d_in[1];
    const float* start_W  = (const float*)d_in[2];
    const float* start_b  = (const float*)d_in[3];
    const float* Wq       = (const float*)d_in[4];
    const float* Wk       = (const float*)d_in[5];
    const float* Wv       = (const float*)d_in[6];
    const float* Wo       = (const float*)d_in[7];
    const float* ln1_g    = (const float*)d_in[8];
    const float* ln1_b    = (const float*)d_in[9];
    const float* ln2_g    = (const float*)d_in[10];
    const float* ln2_b    = (const float*)d_in[11];
    const float* W1       = (const float*)d_in[12];
    const float* b1       = (const float*)d_in[13];
    const float* W2       = (const float*)d_in[14];
    const float* b2       = (const float*)d_in[15];
    float* out = (float*)d_out;

    preprocess_kernel<<<Bz * Nz, 256>>>(x);
    route_pre_kernel<<<2, 256>>>(ox, start_W, start_b, Wq, Wk, Wv, Wo,
                                 ln1_g, ln1_b);
    attn_kernel<<<Bz * Ez * Nz, 256>>>();
    tail1_kernel<<<Bz * Ez * 16, 128>>>(start_W, start_b, ln2_g, ln2_b, b2);
    tail23_kernel<<<Bz * Ez * 16, 128>>>(W1, b1, W2, out);
}